// round 1
// baseline (speedup 1.0000x reference)
#include <cuda_runtime.h>
#include <math.h>

// Problem constants (fixed shapes: xs/hat_xs are (16, 65536, 3) float32)
#define NGROUPS      65536     // 1048576 vectors / 16
#define THREADS      256
#define NBLOCKS      (NGROUPS / THREADS)   // 256
#define PAIRS_MASK   2047      // pairs per batch = 65536/16/2 = 2048
#define N0_DROP      5
#define DT           0.01f
#define INV_HUBER    200.0f    // 1/0.005
// loss = 0.2/65536 * sum(angle^2) + (0.1 * 1e6 * 0.005^2 / 2) / (16*2043*3) * sum(huber)
#define AOE_COEF     (0.2 / 65536.0)
#define HUB_COEF     (1.25 / 98064.0)

__device__ double g_aoe = 0.0;
__device__ double g_hub = 0.0;
__device__ unsigned int g_done = 0;

// Rodrigues: R = I + s*K + c*K^2,  s=sin(a)/a, c=(1-cos a)/a^2.
// Taylor branch for a^2 < 0.01 (covers ALL the DT-scaled phis; rel err ~1e-10).
__device__ __forceinline__ void rodrigues(float x, float y, float z, float R[9]) {
    float a2 = fmaf(x, x, fmaf(y, y, z * z));
    float s, c;
    if (a2 < 1e-2f) {
        s = 1.0f - (a2 * (1.0f / 6.0f))  * (1.0f - a2 * 0.05f);
        c = 0.5f - (a2 * (1.0f / 24.0f)) * (1.0f - a2 * (1.0f / 30.0f));
    } else {
        float a = sqrtf(a2);
        float sa, ca;
        sincosf(a, &sa, &ca);
        s = sa / a;
        c = (1.0f - ca) / a2;
    }
    float cx = c * x, cy = c * y, cz = c * z;
    float sx = s * x, sy = s * y, sz = s * z;
    R[0] = 1.0f - (cy * y + cz * z); R[1] = cx * y - sz;             R[2] = cx * z + sy;
    R[3] = cx * y + sz;              R[4] = 1.0f - (cx * x + cz * z); R[5] = cy * z - sx;
    R[6] = cx * z - sy;              R[7] = cy * z + sx;              R[8] = 1.0f - (cx * x + cy * y);
}

__device__ __forceinline__ void mm(const float A[9], const float B[9], float C[9]) {
#pragma unroll
    for (int i = 0; i < 3; i++) {
#pragma unroll
        for (int k = 0; k < 3; k++) {
            C[3 * i + k] = fmaf(A[3 * i], B[k],
                           fmaf(A[3 * i + 1], B[3 + k],
                                A[3 * i + 2] * B[6 + k]));
        }
    }
}

// acc = acc * exp(DT * v)
__device__ __forceinline__ void chain_step(float A[9], float vx, float vy, float vz) {
    float R[9], T[9];
    rodrigues(DT * vx, DT * vy, DT * vz, R);
    mm(A, R, T);
#pragma unroll
    for (int i = 0; i < 9; i++) A[i] = T[i];
}

__device__ __forceinline__ float huber_elem(float r) {
    float ar = fabsf(r);
    return (ar < 1.0f) ? 0.5f * r * r : ar - 0.5f;
}

__global__ __launch_bounds__(THREADS)
void loss_kernel(const float* __restrict__ xs, const float* __restrict__ hat,
                 float* __restrict__ out) {
    const int n = blockIdx.x * THREADS + threadIdx.x;   // group index, 0..65535

    // ---- chain of 16 exps: read 16 vectors = 12 float4 (contiguous 192B per thread)
    const float4* hp = reinterpret_cast<const float4*>(hat) + (size_t)n * 12;
    float A[9];
    {
        float4 v0 = hp[0], v1 = hp[1], v2 = hp[2];
        rodrigues(DT * v0.x, DT * v0.y, DT * v0.z, A);
        chain_step(A, v0.w, v1.x, v1.y);
        chain_step(A, v1.z, v1.w, v2.x);
        chain_step(A, v2.y, v2.z, v2.w);
    }
#pragma unroll
    for (int chunk = 1; chunk < 4; chunk++) {
        float4 v0 = hp[chunk * 3 + 0], v1 = hp[chunk * 3 + 1], v2 = hp[chunk * 3 + 2];
        chain_step(A, v0.x, v0.y, v0.z);
        chain_step(A, v0.w, v1.x, v1.y);
        chain_step(A, v1.z, v1.w, v2.x);
        chain_step(A, v2.y, v2.z, v2.w);
    }

    // ---- X_n = exp(xs_flat[16n]); xs float index 48n is 16B-aligned
    float X[9];
    {
        float4 xv = reinterpret_cast<const float4*>(xs)[(size_t)n * 12];
        rodrigues(xv.x, xv.y, xv.z, X);
    }

    // ---- AOE: tr(Omega^T X) = elementwise dot
    float tr = 0.0f;
#pragma unroll
    for (int i = 0; i < 9; i++) tr = fmaf(A[i], X[i], tr);
    float ca  = fminf(fmaxf((tr - 1.0f) * 0.5f, -1.0f), 1.0f);
    float ang = acosf(ca);
    float aoe = ang * ang;

    // ---- pair combine (n even pairs with n+1, same warp)
    float Ao[9], Xo[9];
#pragma unroll
    for (int i = 0; i < 9; i++) {
        Ao[i] = __shfl_down_sync(0xffffffffu, A[i], 1);
        Xo[i] = __shfl_down_sync(0xffffffffu, X[i], 1);
    }
    float hub = 0.0f;
    if ((n & 1) == 0) {
        int m = n >> 1;
        if ((m & PAIRS_MASK) >= N0_DROP) {
            float Om[9], Xm[9], Rel[9];
            mm(A, Ao, Om);
            mm(X, Xo, Xm);
            // Rel = Om^T * Xm
#pragma unroll
            for (int i = 0; i < 3; i++) {
#pragma unroll
                for (int k = 0; k < 3; k++) {
                    Rel[3 * i + k] = fmaf(Om[i], Xm[k],
                                     fmaf(Om[3 + i], Xm[3 + k],
                                          Om[6 + i] * Xm[6 + k]));
                }
            }
            float tr2  = Rel[0] + Rel[4] + Rel[8];
            float ca2  = fminf(fmaxf((tr2 - 1.0f) * 0.5f, -1.0f), 1.0f);
            float ang2 = acosf(ca2);
            float sa   = sinf(ang2);
            float factor = (sa < 1e-6f) ? 0.5f : ang2 / (2.0f * sa);
            float fh = factor * INV_HUBER;
            float r0 = fh * (Rel[7] - Rel[5]);
            float r1 = fh * (Rel[2] - Rel[6]);
            float r2 = fh * (Rel[3] - Rel[1]);
            hub = huber_elem(r0) + huber_elem(r1) + huber_elem(r2);
        }
    }

    // ---- warp reduction
#pragma unroll
    for (int o = 16; o > 0; o >>= 1) {
        aoe += __shfl_xor_sync(0xffffffffu, aoe, o);
        hub += __shfl_xor_sync(0xffffffffu, hub, o);
    }

    // ---- block reduction
    __shared__ float s_aoe[THREADS / 32];
    __shared__ float s_hub[THREADS / 32];
    __shared__ bool  s_last;
    int wid = threadIdx.x >> 5;
    int lid = threadIdx.x & 31;
    if (lid == 0) { s_aoe[wid] = aoe; s_hub[wid] = hub; }
    __syncthreads();

    if (threadIdx.x == 0) {
        float ba = 0.0f, bh = 0.0f;
#pragma unroll
        for (int i = 0; i < THREADS / 32; i++) { ba += s_aoe[i]; bh += s_hub[i]; }
        atomicAdd(&g_aoe, (double)ba);
        atomicAdd(&g_hub, (double)bh);
        __threadfence();
        unsigned int old = atomicAdd(&g_done, 1u);
        s_last = (old == (unsigned int)(gridDim.x - 1));
    }
    __syncthreads();

    // ---- last block finalizes: write scalar, reset accumulators for next replay
    if (threadIdx.x == 0 && s_last) {
        double aoe_t = atomicAdd(&g_aoe, 0.0);
        double hub_t = atomicAdd(&g_hub, 0.0);
        out[0] = (float)(AOE_COEF * aoe_t + HUB_COEF * hub_t);
        g_aoe = 0.0;
        g_hub = 0.0;
        __threadfence();
        atomicExch(&g_done, 0u);
    }
}

extern "C" void kernel_launch(void* const* d_in, const int* in_sizes, int n_in,
                              void* d_out, int out_size) {
    const float* xs  = (const float*)d_in[0];
    const float* hat = (const float*)d_in[1];
    (void)in_sizes; (void)n_in; (void)out_size;
    loss_kernel<<<NBLOCKS, THREADS>>>(xs, hat, (float*)d_out);
}

// round 2
// speedup vs baseline: 1.0104x; 1.0104x over previous
#include <cuda_runtime.h>
#include <math.h>

// Fixed shapes: xs/hat_xs are (16, 65536, 3) float32 -> 1,048,576 vectors, 65,536 groups of 16.
#define NGROUPS      65536
#define TPG          2                      // threads per group
#define NTHREADS     (NGROUPS * TPG)        // 131072
#define THREADS      128
#define NBLOCKS      (NTHREADS / THREADS)   // 1024
#define PAIRS_MASK   2047                   // pairs per batch at level k=4
#define N0_DROP      5
#define DT           0.01f
#define INV_HUBER    200.0f
#define AOE_COEF     (0.2 / 65536.0)
#define HUB_COEF     (1.25 / 98064.0)       // 0.1*W*HUBER^2/2 / (16*2043*3)

__device__ double g_aoe = 0.0;
__device__ double g_hub = 0.0;
__device__ unsigned int g_done = 0;

// Branch-free small-angle Rodrigues. Valid to fp32 accuracy for a2 < ~0.1;
// chain inputs are DT*N(0,1) so a2 <= ~0.005 — Taylor error ~1e-12.
__device__ __forceinline__ void rod_small(float x, float y, float z, float R[9]) {
    float a2 = fmaf(x, x, fmaf(y, y, z * z));
    float s = 1.0f - (a2 * (1.0f / 6.0f))  * (1.0f - a2 * 0.05f);
    float c = 0.5f - (a2 * (1.0f / 24.0f)) * (1.0f - a2 * (1.0f / 30.0f));
    float cx = c * x, cy = c * y, cz = c * z;
    float sx = s * x, sy = s * y, sz = s * z;
    R[0] = 1.0f - (cy * y + cz * z); R[1] = cx * y - sz;              R[2] = cx * z + sy;
    R[3] = cx * y + sz;              R[4] = 1.0f - (cx * x + cz * z); R[5] = cy * z - sx;
    R[6] = cx * z - sy;              R[7] = cy * z + sx;              R[8] = 1.0f - (cx * x + cy * y);
}

// Full-range Rodrigues (for X = exp(xs), std-normal magnitude).
__device__ __forceinline__ void rod_full(float x, float y, float z, float R[9]) {
    float a2 = fmaf(x, x, fmaf(y, y, z * z));
    float a2s = fmaxf(a2, 1e-16f);
    float a = sqrtf(a2s);
    float sa, ca;
    sincosf(a, &sa, &ca);
    float s = sa / a;
    float c = (1.0f - ca) / a2s;
    // degenerate-tiny fallback (reference EPS path); predicated, essentially never taken
    if (a2 < 1e-8f) { s = 1.0f - a2 * (1.0f / 6.0f); c = 0.5f - a2 * (1.0f / 24.0f); }
    float cx = c * x, cy = c * y, cz = c * z;
    float sx = s * x, sy = s * y, sz = s * z;
    R[0] = 1.0f - (cy * y + cz * z); R[1] = cx * y - sz;              R[2] = cx * z + sy;
    R[3] = cx * y + sz;              R[4] = 1.0f - (cx * x + cz * z); R[5] = cy * z - sx;
    R[6] = cx * z - sy;              R[7] = cy * z + sx;              R[8] = 1.0f - (cx * x + cy * y);
}

__device__ __forceinline__ void mm(const float A[9], const float B[9], float C[9]) {
#pragma unroll
    for (int i = 0; i < 3; i++)
#pragma unroll
        for (int k = 0; k < 3; k++)
            C[3 * i + k] = fmaf(A[3 * i], B[k],
                           fmaf(A[3 * i + 1], B[3 + k],
                                A[3 * i + 2] * B[6 + k]));
}

// acc = acc * exp(DT * v), branch-free small-angle
__device__ __forceinline__ void chain_step(float A[9], float vx, float vy, float vz) {
    float R[9], T[9];
    rod_small(DT * vx, DT * vy, DT * vz, R);
    mm(A, R, T);
#pragma unroll
    for (int i = 0; i < 9; i++) A[i] = T[i];
}

__device__ __forceinline__ float huber_elem(float r) {
    float ar = fabsf(r);
    return (ar < 1.0f) ? 0.5f * r * r : ar - 0.5f;
}

__global__ __launch_bounds__(THREADS)
void loss_kernel(const float* __restrict__ xs, const float* __restrict__ hat,
                 float* __restrict__ out) {
    const int tid = blockIdx.x * THREADS + threadIdx.x;
    const int t   = tid & 1;        // sub-thread within group
    const int n   = tid >> 1;       // group index 0..65535

    // ---- load this thread's 8 vectors = 6 float4 (96B contiguous), all upfront (MLP=6)
    const float4* hp = reinterpret_cast<const float4*>(hat) + (size_t)n * 12 + t * 6;
    float4 v0 = hp[0], v1 = hp[1], v2 = hp[2], v3 = hp[3], v4 = hp[4], v5 = hp[5];

    // ---- two independent 4-exp chains (ILP 2), then merge
    float P[9], Q[9];
    rod_small(DT * v0.x, DT * v0.y, DT * v0.z, P);
    rod_small(DT * v3.x, DT * v3.y, DT * v3.z, Q);
    chain_step(P, v0.w, v1.x, v1.y);
    chain_step(Q, v3.w, v4.x, v4.y);
    chain_step(P, v1.z, v1.w, v2.x);
    chain_step(Q, v4.z, v4.w, v5.x);
    chain_step(P, v2.y, v2.z, v2.w);
    chain_step(Q, v5.y, v5.z, v5.w);

    float H[9];                      // product of this thread's 8 exps
    mm(P, Q, H);

    // ---- merge partner lane (t=1 -> t=0): Omega for group n lives on even lanes
    float Ho[9];
#pragma unroll
    for (int i = 0; i < 9; i++) Ho[i] = __shfl_down_sync(0xffffffffu, H[i], 1);
    float Om[9];
    mm(H, Ho, Om);                   // valid on even lanes

    // ---- X_n = exp(xs_flat[16n]) on even lanes (odd lanes: no load issued)
    float X[9];
    float4 xv = make_float4(0.f, 0.f, 0.f, 0.f);
    if (t == 0) xv = reinterpret_cast<const float4*>(xs)[(size_t)n * 12];
    rod_full(xv.x, xv.y, xv.z, X);

    // ---- AOE (even lanes)
    float aoe = 0.0f;
    if (t == 0) {
        float tr = 0.0f;
#pragma unroll
        for (int i = 0; i < 9; i++) tr = fmaf(Om[i], X[i], tr);
        float ca  = fminf(fmaxf((tr - 1.0f) * 0.5f, -1.0f), 1.0f);
        float ang = acosf(ca);
        aoe = ang * ang;
    }

    // ---- pyramid level: pair group 2m (lane l, l%4==0) with 2m+1 (lane l+2)
    float Oo[9], Xo[9];
#pragma unroll
    for (int i = 0; i < 9; i++) {
        Oo[i] = __shfl_down_sync(0xffffffffu, Om[i], 2);
        Xo[i] = __shfl_down_sync(0xffffffffu, X[i],  2);
    }
    float hub = 0.0f;
    if (t == 0 && (n & 1) == 0) {
        int m = n >> 1;
        if ((m & PAIRS_MASK) >= N0_DROP) {
            float Op[9], Xp[9], Rel[9];
            mm(Om, Oo, Op);
            mm(X,  Xo, Xp);
            // Rel = Op^T * Xp
#pragma unroll
            for (int i = 0; i < 3; i++)
#pragma unroll
                for (int k = 0; k < 3; k++)
                    Rel[3 * i + k] = fmaf(Op[i], Xp[k],
                                     fmaf(Op[3 + i], Xp[3 + k],
                                          Op[6 + i] * Xp[6 + k]));
            float tr2  = Rel[0] + Rel[4] + Rel[8];
            float ca2  = fminf(fmaxf((tr2 - 1.0f) * 0.5f, -1.0f), 1.0f);
            float ang2 = acosf(ca2);
            float sa   = sinf(ang2);
            float factor = (sa < 1e-6f) ? 0.5f : ang2 / (2.0f * sa);
            float fh = factor * INV_HUBER;
            float r0 = fh * (Rel[7] - Rel[5]);
            float r1 = fh * (Rel[2] - Rel[6]);
            float r2 = fh * (Rel[3] - Rel[1]);
            hub = huber_elem(r0) + huber_elem(r1) + huber_elem(r2);
        }
    }

    // ---- warp reduction
#pragma unroll
    for (int o = 16; o > 0; o >>= 1) {
        aoe += __shfl_xor_sync(0xffffffffu, aoe, o);
        hub += __shfl_xor_sync(0xffffffffu, hub, o);
    }

    // ---- block reduction + global accumulate
    __shared__ float s_aoe[THREADS / 32];
    __shared__ float s_hub[THREADS / 32];
    __shared__ bool  s_last;
    int wid = threadIdx.x >> 5;
    int lid = threadIdx.x & 31;
    if (lid == 0) { s_aoe[wid] = aoe; s_hub[wid] = hub; }
    __syncthreads();

    if (threadIdx.x == 0) {
        float ba = 0.0f, bh = 0.0f;
#pragma unroll
        for (int i = 0; i < THREADS / 32; i++) { ba += s_aoe[i]; bh += s_hub[i]; }
        atomicAdd(&g_aoe, (double)ba);
        atomicAdd(&g_hub, (double)bh);
        __threadfence();
        unsigned int old = atomicAdd(&g_done, 1u);
        s_last = (old == (unsigned int)(gridDim.x - 1));
    }
    __syncthreads();

    if (threadIdx.x == 0 && s_last) {
        double aoe_t = atomicAdd(&g_aoe, 0.0);
        double hub_t = atomicAdd(&g_hub, 0.0);
        out[0] = (float)(AOE_COEF * aoe_t + HUB_COEF * hub_t);
        g_aoe = 0.0;
        g_hub = 0.0;
        __threadfence();
        atomicExch(&g_done, 0u);
    }
}

extern "C" void kernel_launch(void* const* d_in, const int* in_sizes, int n_in,
                              void* d_out, int out_size) {
    const float* xs  = (const float*)d_in[0];
    const float* hat = (const float*)d_in[1];
    (void)in_sizes; (void)n_in; (void)out_size;
    loss_kernel<<<NBLOCKS, THREADS>>>(xs, hat, (float*)d_out);
}

// round 3
// speedup vs baseline: 1.0958x; 1.0845x over previous
#include <cuda_runtime.h>
#include <math.h>

// Fixed shapes: xs/hat_xs are (16, 65536, 3) float32 -> 1,048,576 vectors, 65,536 groups of 16.
#define NGROUPS      65536
#define TPG          4                      // threads per group (4 exps each)
#define NTHREADS     (NGROUPS * TPG)        // 262144
#define THREADS      256
#define NBLOCKS      (NTHREADS / THREADS)   // 1024
#define PAIRS_MASK   2047
#define N0_DROP      5
#define DT           0.01f
#define INV_HUBER    200.0f
#define AOE_COEF     (0.2 / 65536.0)
#define HUB_COEF     (1.25 / 98064.0)       // 0.1*W*HUBER^2/2 / (16*2043*3)

__device__ double g_aoe = 0.0;
__device__ double g_hub = 0.0;
__device__ unsigned int g_done = 0;

// q = (x,y,z,w): w scalar part. Hamilton product (rotation composition R(a)R(b)).
__device__ __forceinline__ float4 qmul(float4 a, float4 b) {
    float4 r;
    r.w = a.w * b.w - a.x * b.x - a.y * b.y - a.z * b.z;
    r.x = a.w * b.x + a.x * b.w + a.y * b.z - a.z * b.y;
    r.y = a.w * b.y - a.x * b.z + a.y * b.w + a.z * b.x;
    r.z = a.w * b.z + a.x * b.y - a.y * b.x + a.z * b.w;
    return r;
}

// conj(a) * b  (relative rotation a^T b)
__device__ __forceinline__ float4 qcmul(float4 a, float4 b) {
    float4 r;
    r.w = a.w * b.w + a.x * b.x + a.y * b.y + a.z * b.z;
    r.x = a.w * b.x - a.x * b.w - a.y * b.z + a.z * b.y;
    r.y = a.w * b.y + a.x * b.z - a.y * b.w - a.z * b.x;
    r.z = a.w * b.z - a.x * b.y + a.y * b.x - a.z * b.w;
    return r;
}

// exp of small rotation vector (|v| <= ~0.1): Taylor in t2=(a/2)^2, error ~1e-12.
__device__ __forceinline__ float4 qexp_small(float x, float y, float z) {
    float a2 = fmaf(x, x, fmaf(y, y, z * z));
    float t2 = 0.25f * a2;
    float w  = fmaf(t2, fmaf(t2, (1.0f / 24.0f), -0.5f), 1.0f);          // cos(a/2)
    float k  = fmaf(t2, fmaf(t2, (0.5f / 120.0f), -(0.5f / 6.0f)), 0.5f); // sin(a/2)/a
    return make_float4(k * x, k * y, k * z, w);
}

// exp of full-range rotation vector (for X = exp(xs))
__device__ __forceinline__ float4 qexp_full(float x, float y, float z) {
    float a2 = fmaf(x, x, fmaf(y, y, z * z));
    float a  = sqrtf(fmaxf(a2, 1e-16f));
    float s, c;
    sincosf(0.5f * a, &s, &c);
    float k = s / a;
    if (a2 < 1e-8f) k = 0.5f;   // reference EPS branch (predicated, ~never taken)
    return make_float4(k * x, k * y, k * z, c);
}

__device__ __forceinline__ float huber_elem(float r) {
    float ar = fabsf(r);
    return (ar < 1.0f) ? 0.5f * r * r : ar - 0.5f;
}

__global__ __launch_bounds__(THREADS)
void loss_kernel(const float* __restrict__ xs, const float* __restrict__ hat,
                 float* __restrict__ out) {
    const int tid = blockIdx.x * THREADS + threadIdx.x;
    const int t   = tid & 3;        // sub-thread within group (handles vectors 4t..4t+3)
    const int n   = tid >> 2;       // group index 0..65535

    // ---- load 4 vectors = 3 float4 (48B contiguous per thread)
    const float4* hp = reinterpret_cast<const float4*>(hat) + (size_t)n * 12 + t * 3;
    float4 v0 = hp[0], v1 = hp[1], v2 = hp[2];

    // ---- 4 small exps, tree-combined (2 independent qmuls, then 1)
    float4 qa = qexp_small(DT * v0.x, DT * v0.y, DT * v0.z);
    float4 qb = qexp_small(DT * v0.w, DT * v1.x, DT * v1.y);
    float4 qc = qexp_small(DT * v1.z, DT * v1.w, DT * v2.x);
    float4 qd = qexp_small(DT * v2.y, DT * v2.z, DT * v2.w);
    float4 H  = qmul(qmul(qa, qb), qmul(qc, qd));   // product of this thread's 4 exps

    // ---- merge within group: Om = H0*H1*H2*H3 (valid on t==0 lanes)
    float4 Ho, G1, G2o, Om;
    Ho.x = __shfl_down_sync(0xffffffffu, H.x, 1);
    Ho.y = __shfl_down_sync(0xffffffffu, H.y, 1);
    Ho.z = __shfl_down_sync(0xffffffffu, H.z, 1);
    Ho.w = __shfl_down_sync(0xffffffffu, H.w, 1);
    G1 = qmul(H, Ho);                                // valid on even t
    G2o.x = __shfl_down_sync(0xffffffffu, G1.x, 2);
    G2o.y = __shfl_down_sync(0xffffffffu, G1.y, 2);
    G2o.z = __shfl_down_sync(0xffffffffu, G1.z, 2);
    G2o.w = __shfl_down_sync(0xffffffffu, G1.w, 2);
    Om = qmul(G1, G2o);                              // valid on t==0

    // ---- X_n = exp(xs_flat[16n]) on t==0 lanes
    float4 xv = make_float4(0.f, 0.f, 0.f, 0.f);
    if (t == 0) xv = reinterpret_cast<const float4*>(xs)[(size_t)n * 12];
    float4 X = qexp_full(xv.x, xv.y, xv.z);

    // ---- AOE: cos(theta/2) = |<qOm, qX>|
    float aoe = 0.0f;
    if (t == 0) {
        float d = fmaf(Om.w, X.w, fmaf(Om.x, X.x, fmaf(Om.y, X.y, Om.z * X.z)));
        float ch = fminf(fabsf(d), 1.0f);
        float ang = 2.0f * acosf(ch);
        aoe = ang * ang;
    }

    // ---- pyramid level: pair group 2m (lane base 8m%32) with 2m+1 (lane +4)
    float4 Omo, Xo;
    Omo.x = __shfl_down_sync(0xffffffffu, Om.x, 4);
    Omo.y = __shfl_down_sync(0xffffffffu, Om.y, 4);
    Omo.z = __shfl_down_sync(0xffffffffu, Om.z, 4);
    Omo.w = __shfl_down_sync(0xffffffffu, Om.w, 4);
    Xo.x  = __shfl_down_sync(0xffffffffu, X.x, 4);
    Xo.y  = __shfl_down_sync(0xffffffffu, X.y, 4);
    Xo.z  = __shfl_down_sync(0xffffffffu, X.z, 4);
    Xo.w  = __shfl_down_sync(0xffffffffu, X.w, 4);

    float hub = 0.0f;
    if (t == 0 && (n & 1) == 0) {
        int m = n >> 1;
        if ((m & PAIRS_MASK) >= N0_DROP) {
            float4 Op  = qmul(Om, Omo);
            float4 Xp  = qmul(X, Xo);
            float4 rel = qcmul(Op, Xp);              // Op^T * Xp
            float w = rel.w;
            // cos(theta) = 2w^2-1 (== (tr-1)/2); sin(theta) = 2|w|sqrt(1-w^2)
            float ct = fminf(fmaxf(fmaf(2.0f * w, w, -1.0f), -1.0f), 1.0f);
            float ang = acosf(ct);
            float sv  = sqrtf(fmaxf(1.0f - w * w, 0.0f));
            float st  = 2.0f * fabsf(w) * sv;
            float factor = (st < 1e-6f) ? 0.5f : ang / (2.0f * st);
            float fh = factor * 4.0f * w * INV_HUBER;
            hub = huber_elem(fh * rel.x) + huber_elem(fh * rel.y) + huber_elem(fh * rel.z);
        }
    }

    // ---- warp reduction
#pragma unroll
    for (int o = 16; o > 0; o >>= 1) {
        aoe += __shfl_xor_sync(0xffffffffu, aoe, o);
        hub += __shfl_xor_sync(0xffffffffu, hub, o);
    }

    // ---- block reduction + global accumulate
    __shared__ float s_aoe[THREADS / 32];
    __shared__ float s_hub[THREADS / 32];
    __shared__ bool  s_last;
    int wid = threadIdx.x >> 5;
    int lid = threadIdx.x & 31;
    if (lid == 0) { s_aoe[wid] = aoe; s_hub[wid] = hub; }
    __syncthreads();

    if (threadIdx.x == 0) {
        float ba = 0.0f, bh = 0.0f;
#pragma unroll
        for (int i = 0; i < THREADS / 32; i++) { ba += s_aoe[i]; bh += s_hub[i]; }
        atomicAdd(&g_aoe, (double)ba);
        atomicAdd(&g_hub, (double)bh);
        __threadfence();
        unsigned int old = atomicAdd(&g_done, 1u);
        s_last = (old == (unsigned int)(gridDim.x - 1));
    }
    __syncthreads();

    if (threadIdx.x == 0 && s_last) {
        double aoe_t = atomicAdd(&g_aoe, 0.0);
        double hub_t = atomicAdd(&g_hub, 0.0);
        out[0] = (float)(AOE_COEF * aoe_t + HUB_COEF * hub_t);
        g_aoe = 0.0;
        g_hub = 0.0;
        __threadfence();
        atomicExch(&g_done, 0u);
    }
}

extern "C" void kernel_launch(void* const* d_in, const int* in_sizes, int n_in,
                              void* d_out, int out_size) {
    const float* xs  = (const float*)d_in[0];
    const float* hat = (const float*)d_in[1];
    (void)in_sizes; (void)n_in; (void)out_size;
    loss_kernel<<<NBLOCKS, THREADS>>>(xs, hat, (float*)d_out);
}